// round 9
// baseline (speedup 1.0000x reference)
#include <cuda_runtime.h>
#include <cuda_bf16.h>
#include <cstdint>

#define Bn 8
#define Ln 2500
#define Dn 512
#define Yn 8921
#define YT 128          // y per CTA
#define LT 64           // l per CTA tile
#define KC 32           // k per chunk (bf16 elems)
#define NCH (Dn / KC)   // 16 chunks
#define NTILES 40       // ceil(2500/64)
#define NT 256
#define ROWB 80                     // smem row stride bytes (32 bf16 + 16 pad)
#define TW (128 * ROWB)             // 10240 (W tiles: 128 rows)
#define TX (64 * ROWB)              // 5120  (X tiles: 64 rows)
#define OFF_UH 0
#define OFF_UL TW
#define OFF_FH (2 * TW)
#define OFF_FL (3 * TW)
#define OFF_XH (4 * TW)
#define OFF_XL (4 * TW + TX)
#define BUF_BYTES (4 * TW + 2 * TX) // 51200
#define SMEM_BYTES (2 * BUF_BYTES)  // 102400  -> 2 CTAs/SM

// bf16 hi/lo scratch (device globals; no runtime alloc)
__device__ __nv_bfloat16 g_xh[(size_t)Bn * Ln * Dn];
__device__ __nv_bfloat16 g_xl[(size_t)Bn * Ln * Dn];
__device__ __nv_bfloat16 g_uh[(size_t)Yn * Dn];
__device__ __nv_bfloat16 g_ul[(size_t)Yn * Dn];
__device__ __nv_bfloat16 g_fh[(size_t)Yn * Dn];
__device__ __nv_bfloat16 g_fl[(size_t)Yn * Dn];

// mma.sync m16n8k16 bf16 (plain sm_80+ instruction)
#define MMA(D, A, B0, B1)                                                   \
    asm volatile(                                                           \
        "mma.sync.aligned.m16n8k16.row.col.f32.bf16.bf16.f32 "              \
        "{%0,%1,%2,%3}, {%4,%5,%6,%7}, {%8,%9}, {%0,%1,%2,%3};"             \
        : "+f"((D)[0]), "+f"((D)[1]), "+f"((D)[2]), "+f"((D)[3])            \
        : "r"((A)[0]), "r"((A)[1]), "r"((A)[2]), "r"((A)[3]),               \
          "r"(B0), "r"(B1))

#define LDSM4(R0, R1, R2, R3, addr)                                         \
    asm volatile(                                                           \
        "ldmatrix.sync.aligned.m8n8.x4.shared.b16 {%0,%1,%2,%3}, [%4];"     \
        : "=r"(R0), "=r"(R1), "=r"(R2), "=r"(R3) : "r"(addr))

static __device__ __forceinline__ void cp16(uint32_t dst, const void* src,
                                            bool v) {
    int sz = v ? 16 : 0;   // sz=0 -> zero-fill 16B, no gmem read
    asm volatile("cp.async.cg.shared.global [%0], [%1], 16, %2;"
                 :: "r"(dst), "l"(src), "r"(sz));
}
template <int N>
static __device__ __forceinline__ void cpwait() {
    asm volatile("cp.async.wait_group %0;" :: "n"(N) : "memory");
}
static __device__ __forceinline__ uint32_t smem_u32(const void* p) {
    uint32_t a;
    asm("{ .reg .u64 t; cvta.to.shared.u64 t, %1; cvt.u32.u64 %0, t; }"
        : "=r"(a) : "l"(p));
    return a;
}

// stage one k-chunk: 4 W tiles [128 x 32] + 2 X tiles [64 x 32] bf16
static __device__ __forceinline__ void stage_chunk(
    uint32_t bufaddr, int tid, int b, int y0, int l0, int k0)
{
    const __nv_bfloat16* w[4] = {
        g_uh + (size_t)y0 * Dn, g_ul + (size_t)y0 * Dn,
        g_fh + (size_t)y0 * Dn, g_fl + (size_t)y0 * Dn };
    const int limW = Yn - y0;
#pragma unroll
    for (int sub = 0; sub < 4; sub++) {
#pragma unroll
        for (int j = 0; j < 2; j++) {
            int idx = tid + j * NT;              // 0..511 = 128 rows x 4 segs
            int r = idx >> 2, seg = idx & 3;     // seg = 16B (8 bf16)
            cp16(bufaddr + sub * TW + (uint32_t)(r * ROWB + seg * 16),
                 w[sub] + (size_t)r * Dn + k0 + seg * 8, r < limW);
        }
    }
    const __nv_bfloat16* xh = g_xh + ((size_t)b * Ln + l0) * Dn;
    const __nv_bfloat16* xl = g_xl + ((size_t)b * Ln + l0) * Dn;
    const int limX = Ln - l0;
    {
        int r = tid >> 2, seg = tid & 3;         // 256 = 64 rows x 4 segs
        uint32_t doff = (uint32_t)(r * ROWB + seg * 16);
        cp16(bufaddr + OFF_XH + doff, xh + (size_t)r * Dn + k0 + seg * 8, r < limX);
        cp16(bufaddr + OFF_XL + doff, xl + (size_t)r * Dn + k0 + seg * 8, r < limX);
    }
    asm volatile("cp.async.commit_group;" ::: "memory");
}

__global__ __launch_bounds__(NT, 2)
void attn_mma_kernel(const float* __restrict__ f_b, float* __restrict__ out)
{
    extern __shared__ float smem[];
    const uint32_t sbase = smem_u32(smem);
    const int tid  = threadIdx.x;
    const int lane = tid & 31;
    const int g    = lane >> 2;          // group id 0..7
    const int tg   = lane & 3;           // thread in group 0..3
    const int wid  = tid >> 5;
    const int wy   = wid >> 1;           // warp y index 0..3 (32 y each)
    const int wl   = wid & 1;            // warp l index 0..1 (32 l each)
    const int b    = blockIdx.y;
    const int y0   = blockIdx.x * YT;

    // ldmatrix per-lane address components (bytes)
    const int quad = lane >> 3, r8 = lane & 7;
    const uint32_t laneA = (uint32_t)((r8 + (quad & 1) * 8) * ROWB + (quad >> 1) * 16);
    const uint32_t laneB = (uint32_t)((r8 + (quad >> 1) * 8) * ROWB + (quad & 1) * 16);
    uint32_t aRow[2], bRow[2];
#pragma unroll
    for (int a = 0; a < 2; a++)  aRow[a]  = (uint32_t)((wy * 32 + a * 16) * ROWB) + laneA;
#pragma unroll
    for (int cp = 0; cp < 2; cp++) bRow[cp] = (uint32_t)((wl * 32 + cp * 16) * ROWB) + laneB;

    // running softmax sums for this thread's 4 y rows
    float ss[4] = {0.f, 0.f, 0.f, 0.f};
    float zz[4] = {0.f, 0.f, 0.f, 0.f};

    stage_chunk(sbase, tid, b, y0, 0, 0);   // tile 0, chunk 0 -> buf 0

    for (int t = 0; t < NTILES; t++) {
        const int l0 = t * LT;

        float dS[2][4][4], dT[2][4][4];
#pragma unroll
        for (int a = 0; a < 2; a++)
#pragma unroll
            for (int c = 0; c < 4; c++)
#pragma unroll
                for (int r = 0; r < 4; r++) { dS[a][c][r] = 0.f; dT[a][c][r] = 0.f; }

        for (int ch = 0; ch < NCH; ch++) {
            cpwait<0>();
            __syncthreads();   // all warps done with the other buffer

            const bool last_all = (t == NTILES - 1) && (ch == NCH - 1);
            if (!last_all) {
                int nl0 = (ch == NCH - 1) ? l0 + LT : l0;
                int nk0 = (ch == NCH - 1) ? 0 : (ch + 1) * KC;
                stage_chunk(sbase + ((ch + 1) & 1) * BUF_BYTES, tid, b, y0, nl0, nk0);
            }

            const uint32_t bufb = sbase + (ch & 1) * BUF_BYTES;

#pragma unroll
            for (int ka = 0; ka < 2; ka++) {        // two k16 steps
                const uint32_t kao = (uint32_t)(ka * 32);
                uint32_t auh[2][4], aul[2][4], afh[2][4], afl[2][4];
#pragma unroll
                for (int a = 0; a < 2; a++) {
                    uint32_t ab = bufb + aRow[a] + kao;
                    LDSM4(auh[a][0], auh[a][1], auh[a][2], auh[a][3], ab + OFF_UH);
                    LDSM4(aul[a][0], aul[a][1], aul[a][2], aul[a][3], ab + OFF_UL);
                    LDSM4(afh[a][0], afh[a][1], afh[a][2], afh[a][3], ab + OFF_FH);
                    LDSM4(afl[a][0], afl[a][1], afl[a][2], afl[a][3], ab + OFF_FL);
                }
                uint32_t bh[4][2], bl[4][2];
#pragma unroll
                for (int cp = 0; cp < 2; cp++) {
                    uint32_t bb = bufb + bRow[cp] + kao;
                    LDSM4(bh[2*cp][0], bh[2*cp][1], bh[2*cp+1][0], bh[2*cp+1][1],
                          bb + OFF_XH);
                    LDSM4(bl[2*cp][0], bl[2*cp][1], bl[2*cp+1][0], bl[2*cp+1][1],
                          bb + OFF_XL);
                }
                // term-major: long same-accumulator reuse distance
#pragma unroll
                for (int a = 0; a < 2; a++)
#pragma unroll
                    for (int c = 0; c < 4; c++) MMA(dS[a][c], auh[a], bh[c][0], bh[c][1]);
#pragma unroll
                for (int a = 0; a < 2; a++)
#pragma unroll
                    for (int c = 0; c < 4; c++) MMA(dT[a][c], afh[a], bh[c][0], bh[c][1]);
#pragma unroll
                for (int a = 0; a < 2; a++)
#pragma unroll
                    for (int c = 0; c < 4; c++) MMA(dS[a][c], auh[a], bl[c][0], bl[c][1]);
#pragma unroll
                for (int a = 0; a < 2; a++)
#pragma unroll
                    for (int c = 0; c < 4; c++) MMA(dT[a][c], afh[a], bl[c][0], bl[c][1]);
#pragma unroll
                for (int a = 0; a < 2; a++)
#pragma unroll
                    for (int c = 0; c < 4; c++) MMA(dS[a][c], aul[a], bh[c][0], bh[c][1]);
#pragma unroll
                for (int a = 0; a < 2; a++)
#pragma unroll
                    for (int c = 0; c < 4; c++) MMA(dT[a][c], afl[a], bh[c][0], bh[c][1]);
            }
        }

        // epilogue (regs only) — overlaps the in-flight prefetch of next tile
#pragma unroll
        for (int a = 0; a < 2; a++)
#pragma unroll
            for (int c = 0; c < 4; c++)
#pragma unroll
                for (int r2 = 0; r2 < 2; r2++) {
                    int le = l0 + wl * 32 + c * 8 + 2 * tg;
                    float s0 = dS[a][c][r2 * 2],     t0 = dT[a][c][r2 * 2];
                    float s1 = dS[a][c][r2 * 2 + 1], t1 = dT[a][c][r2 * 2 + 1];
                    if (le < Ln)     { float e = __expf(s0); ss[a*2+r2] += e; zz[a*2+r2] += e * t0; }
                    if (le + 1 < Ln) { float e = __expf(s1); ss[a*2+r2] += e; zz[a*2+r2] += e * t1; }
                }
    }

    // reduce across the 4 lanes sharing each y row (tg dimension)
#pragma unroll
    for (int i = 0; i < 4; i++) {
        ss[i] += __shfl_xor_sync(0xffffffffu, ss[i], 1);
        ss[i] += __shfl_xor_sync(0xffffffffu, ss[i], 2);
        zz[i] += __shfl_xor_sync(0xffffffffu, zz[i], 1);
        zz[i] += __shfl_xor_sync(0xffffffffu, zz[i], 2);
    }

    // cross-warp (wl) reduction via smem (all staging finished by now)
    __syncthreads();
    float* sred = smem;          // [2][128]
    float* zred = smem + 256;    // [2][128]
    if (tg == 0) {
#pragma unroll
        for (int i = 0; i < 4; i++) {
            int yl = wy * 32 + (i >> 1) * 16 + (i & 1) * 8 + g;
            sred[wl * 128 + yl] = ss[i];
            zred[wl * 128 + yl] = zz[i];
        }
    }
    __syncthreads();
    if (tid < 128) {
        int yg = y0 + tid;
        if (yg < Yn) {
            float s = sred[tid] + sred[128 + tid];
            float z = zred[tid] + zred[128 + tid];
            out[(size_t)b * Yn + yg] = z / s + f_b[yg];
        }
    }
}

// ---------------- prepass: fp32 -> bf16 hi/lo ----------------
static __device__ __forceinline__ void split2(float v, __nv_bfloat16* h,
                                              __nv_bfloat16* l) {
    __nv_bfloat16 hh = __float2bfloat16(v);
    *h = hh;
    *l = __float2bfloat16(v - __bfloat162float(hh));
}

__global__ void prep_w(const float* __restrict__ U, const float* __restrict__ F)
{
    const size_t n = (size_t)Yn * Dn;
    for (size_t i = (size_t)blockIdx.x * blockDim.x + threadIdx.x; i < n;
         i += (size_t)gridDim.x * blockDim.x) {
        split2(U[i], &g_uh[i], &g_ul[i]);
        split2(F[i], &g_fh[i], &g_fl[i]);
    }
}

__global__ void prep_x(const float* __restrict__ x)
{
    const size_t n = (size_t)Bn * Ln * Dn;
    for (size_t i = (size_t)blockIdx.x * blockDim.x + threadIdx.x; i < n;
         i += (size_t)gridDim.x * blockDim.x)
        split2(x[i], &g_xh[i], &g_xl[i]);
}

// mean BCE-with-logits; single block, fixed-order -> deterministic
__global__ void bce_kernel(const float* __restrict__ y,
                           const float* __restrict__ t,
                           float* __restrict__ loss_out, int n)
{
    __shared__ float red[1024];
    float acc = 0.f;
    for (int i = threadIdx.x; i < n; i += 1024) {
        float v  = y[i];
        float tt = t[i];
        acc += fmaxf(v, 0.f) - v * tt + log1pf(__expf(-fabsf(v)));
    }
    red[threadIdx.x] = acc;
    __syncthreads();
    for (int s = 512; s > 0; s >>= 1) {
        if (threadIdx.x < s) red[threadIdx.x] += red[threadIdx.x + s];
        __syncthreads();
    }
    if (threadIdx.x == 0) loss_out[0] = red[0] / (float)n;
}

extern "C" void kernel_launch(void* const* d_in, const int* in_sizes, int n_in,
                              void* d_out, int out_size)
{
    const float* x      = (const float*)d_in[0];
    const float* target = (const float*)d_in[1];
    // d_in[2] = text_inputs (unused)
    const float* U_w    = (const float*)d_in[3];
    const float* F_w    = (const float*)d_in[4];
    const float* f_b    = (const float*)d_in[5];
    float* out = (float*)d_out;

    cudaFuncSetAttribute(attn_mma_kernel,
                         cudaFuncAttributeMaxDynamicSharedMemorySize, SMEM_BYTES);

    prep_w<<<1024, 256>>>(U_w, F_w);
    prep_x<<<2048, 256>>>(x);

    dim3 grid((Yn + YT - 1) / YT, Bn);   // 70 x 8 = 560 CTAs, 2/SM
    attn_mma_kernel<<<grid, NT, SMEM_BYTES>>>(f_b, out);

    if (out_size > Bn * Yn)
        bce_kernel<<<1, 1024>>>(out, target, out + Bn * Yn, Bn * Yn);
}

// round 10
// speedup vs baseline: 2.7900x; 2.7900x over previous
#include <cuda_runtime.h>
#include <cuda_fp16.h>
#include <cstdint>

#define Bn 8
#define Ln 2500
#define Dn 512
#define Yn 8921
#define YT 128          // y per CTA
#define LT 128          // l per CTA tile
#define KC 128          // k per chunk (fp16 elems)
#define NCH (Dn / KC)   // 4 chunks
#define NTILES 20       // ceil(2500/128)
#define NT 256
#define ROWB 272                    // smem row stride bytes (256 data + 16 pad)
#define TILE_BYTES (128 * ROWB)     // 34816
#define BUF_BYTES (3 * TILE_BYTES)  // 104448 : U F X
#define SMEM_BYTES (2 * BUF_BYTES)  // 208896

// fp16 scratch (device globals; no runtime alloc)
__device__ __half g_u16[(size_t)Yn * Dn];
__device__ __half g_f16[(size_t)Yn * Dn];
__device__ __half g_x16[(size_t)Bn * Ln * Dn];

// mma.sync m16n8k16 fp16 inputs, fp32 accumulate (plain sm_80+ instruction)
#define MMA(D, A, B0, B1)                                                   \
    asm volatile(                                                           \
        "mma.sync.aligned.m16n8k16.row.col.f32.f16.f16.f32 "                \
        "{%0,%1,%2,%3}, {%4,%5,%6,%7}, {%8,%9}, {%0,%1,%2,%3};"             \
        : "+f"((D)[0]), "+f"((D)[1]), "+f"((D)[2]), "+f"((D)[3])            \
        : "r"((A)[0]), "r"((A)[1]), "r"((A)[2]), "r"((A)[3]),               \
          "r"(B0), "r"(B1))

#define LDSM4(R0, R1, R2, R3, addr)                                         \
    asm volatile(                                                           \
        "ldmatrix.sync.aligned.m8n8.x4.shared.b16 {%0,%1,%2,%3}, [%4];"     \
        : "=r"(R0), "=r"(R1), "=r"(R2), "=r"(R3) : "r"(addr))

static __device__ __forceinline__ void cp16(uint32_t dst, const void* src,
                                            bool v) {
    int sz = v ? 16 : 0;   // sz=0 -> zero-fill 16B, no gmem read
    asm volatile("cp.async.cg.shared.global [%0], [%1], 16, %2;"
                 :: "r"(dst), "l"(src), "r"(sz));
}
template <int N>
static __device__ __forceinline__ void cpwait() {
    asm volatile("cp.async.wait_group %0;" :: "n"(N) : "memory");
}
static __device__ __forceinline__ uint32_t smem_u32(const void* p) {
    uint32_t a;
    asm("{ .reg .u64 t; cvta.to.shared.u64 t, %1; cvt.u32.u64 %0, t; }"
        : "=r"(a) : "l"(p));
    return a;
}

// stage one k-chunk: 3 fp16 tiles [128 rows x 128 k] -> padded smem
static __device__ __forceinline__ void stage_chunk(
    uint32_t bufaddr, int tid, int b, int y0, int l0, int k0)
{
    const __half* srcs[3] = {
        g_u16 + (size_t)y0 * Dn,
        g_f16 + (size_t)y0 * Dn,
        g_x16 + ((size_t)b * Ln + l0) * Dn };
#pragma unroll
    for (int sub = 0; sub < 3; sub++) {
        const __half* src = srcs[sub];
        const int lim = (sub < 2) ? (Yn - y0) : (Ln - l0);
#pragma unroll
        for (int j = 0; j < 8; j++) {
            int idx = tid + j * NT;              // 0..2047 = 128 rows x 16 segs
            int r = idx >> 4, seg = idx & 15;    // seg = 16B (8 fp16)
            cp16(bufaddr + sub * TILE_BYTES + (uint32_t)(r * ROWB + seg * 16),
                 src + (size_t)r * Dn + k0 + seg * 8, r < lim);
        }
    }
    asm volatile("cp.async.commit_group;" ::: "memory");
}

__global__ __launch_bounds__(NT)
void attn_mma_kernel(const float* __restrict__ f_b, float* __restrict__ out)
{
    extern __shared__ float smem[];
    const uint32_t sbase = smem_u32(smem);
    const int tid  = threadIdx.x;
    const int lane = tid & 31;
    const int g    = lane >> 2;          // group id 0..7
    const int tg   = lane & 3;           // thread in group 0..3
    const int wid  = tid >> 5;
    const int wy   = wid >> 1;           // warp y index 0..3 (32 y each)
    const int wl   = wid & 1;            // warp l index 0..1 (64 l each)
    const int b    = blockIdx.y;
    const int y0   = blockIdx.x * YT;

    // ldmatrix per-lane address components (bytes)
    const int quad = lane >> 3, r8 = lane & 7;
    const uint32_t laneA = (uint32_t)((r8 + (quad & 1) * 8) * ROWB + (quad >> 1) * 16);
    const uint32_t laneB = (uint32_t)((r8 + (quad >> 1) * 8) * ROWB + (quad & 1) * 16);
    uint32_t aRow[2], bRow[4];
#pragma unroll
    for (int a = 0; a < 2; a++) aRow[a] = (uint32_t)((wy * 32 + a * 16) * ROWB) + laneA;
#pragma unroll
    for (int cp = 0; cp < 4; cp++) bRow[cp] = (uint32_t)((wl * 64 + cp * 16) * ROWB) + laneB;

    // running softmax sums for this thread's 4 y rows
    float ss[4] = {0.f, 0.f, 0.f, 0.f};
    float zz[4] = {0.f, 0.f, 0.f, 0.f};

    stage_chunk(sbase, tid, b, y0, 0, 0);   // tile 0, chunk 0 -> buf 0

    for (int t = 0; t < NTILES; t++) {
        const int l0 = t * LT;

        float dS[2][8][4], dT[2][8][4];
#pragma unroll
        for (int a = 0; a < 2; a++)
#pragma unroll
            for (int c = 0; c < 8; c++)
#pragma unroll
                for (int r = 0; r < 4; r++) { dS[a][c][r] = 0.f; dT[a][c][r] = 0.f; }

        for (int ch = 0; ch < NCH; ch++) {
            cpwait<0>();
            __syncthreads();   // all warps done with the other buffer

            const bool last_all = (t == NTILES - 1) && (ch == NCH - 1);
            if (!last_all) {
                // prefetch next chunk (possibly next tile's chunk 0);
                // overlaps with this chunk's mma block
                int nl0 = (ch == NCH - 1) ? l0 + LT : l0;
                int nk0 = (ch == NCH - 1) ? 0 : (ch + 1) * KC;
                stage_chunk(sbase + ((ch + 1) & 1) * BUF_BYTES, tid, b, y0, nl0, nk0);
            }

            const uint32_t bufb = sbase + (ch & 1) * BUF_BYTES;

#pragma unroll
            for (int ka = 0; ka < 8; ka++) {        // eight k16 steps
                const uint32_t kao = (uint32_t)(ka * 32);
                uint32_t au[2][4], af[2][4];
#pragma unroll
                for (int a = 0; a < 2; a++) {
                    uint32_t ab = bufb + aRow[a] + kao;
                    LDSM4(au[a][0], au[a][1], au[a][2], au[a][3], ab);
                    LDSM4(af[a][0], af[a][1], af[a][2], af[a][3], ab + TILE_BYTES);
                }
                uint32_t bx[8][2];
#pragma unroll
                for (int cp = 0; cp < 4; cp++) {
                    uint32_t bb = bufb + 2 * TILE_BYTES + bRow[cp] + kao;
                    LDSM4(bx[2*cp][0], bx[2*cp][1], bx[2*cp+1][0], bx[2*cp+1][1], bb);
                }
#pragma unroll
                for (int a = 0; a < 2; a++)
#pragma unroll
                    for (int c = 0; c < 8; c++) MMA(dS[a][c], au[a], bx[c][0], bx[c][1]);
#pragma unroll
                for (int a = 0; a < 2; a++)
#pragma unroll
                    for (int c = 0; c < 8; c++) MMA(dT[a][c], af[a], bx[c][0], bx[c][1]);
            }
        }

        // epilogue (regs only) — overlaps the in-flight prefetch of next tile
#pragma unroll
        for (int a = 0; a < 2; a++)
#pragma unroll
            for (int c = 0; c < 8; c++)
#pragma unroll
                for (int r2 = 0; r2 < 2; r2++) {
                    int le = l0 + wl * 64 + c * 8 + 2 * tg;
                    float s0 = dS[a][c][r2 * 2],     t0 = dT[a][c][r2 * 2];
                    float s1 = dS[a][c][r2 * 2 + 1], t1 = dT[a][c][r2 * 2 + 1];
                    if (le < Ln)     { float e = __expf(s0); ss[a*2+r2] += e; zz[a*2+r2] += e * t0; }
                    if (le + 1 < Ln) { float e = __expf(s1); ss[a*2+r2] += e; zz[a*2+r2] += e * t1; }
                }
    }

    // reduce across the 4 lanes sharing each y row (tg dimension)
#pragma unroll
    for (int i = 0; i < 4; i++) {
        ss[i] += __shfl_xor_sync(0xffffffffu, ss[i], 1);
        ss[i] += __shfl_xor_sync(0xffffffffu, ss[i], 2);
        zz[i] += __shfl_xor_sync(0xffffffffu, zz[i], 1);
        zz[i] += __shfl_xor_sync(0xffffffffu, zz[i], 2);
    }

    // cross-warp (wl) reduction via smem (all staging finished by now)
    __syncthreads();
    float* sred = smem;          // [2][128]
    float* zred = smem + 256;    // [2][128]
    if (tg == 0) {
#pragma unroll
        for (int i = 0; i < 4; i++) {
            int yl = wy * 32 + (i >> 1) * 16 + (i & 1) * 8 + g;
            sred[wl * 128 + yl] = ss[i];
            zred[wl * 128 + yl] = zz[i];
        }
    }
    __syncthreads();
    if (tid < 128) {
        int yg = y0 + tid;
        if (yg < Yn) {
            float s = sred[tid] + sred[128 + tid];
            float z = zred[tid] + zred[128 + tid];
            out[(size_t)b * Yn + yg] = z / s + f_b[yg];
        }
    }
}

// ---------------- prepass: fp32 -> fp16 ----------------
__global__ void prep_w(const float* __restrict__ U, const float* __restrict__ F)
{
    const size_t n = (size_t)Yn * Dn;
    for (size_t i = (size_t)blockIdx.x * blockDim.x + threadIdx.x; i < n;
         i += (size_t)gridDim.x * blockDim.x) {
        g_u16[i] = __float2half_rn(U[i]);
        g_f16[i] = __float2half_rn(F[i]);
    }
}

__global__ void prep_x(const float* __restrict__ x)
{
    const size_t n = (size_t)Bn * Ln * Dn;
    for (size_t i = (size_t)blockIdx.x * blockDim.x + threadIdx.x; i < n;
         i += (size_t)gridDim.x * blockDim.x)
        g_x16[i] = __float2half_rn(x[i]);
}

// mean BCE-with-logits; single block, fixed-order -> deterministic
__global__ void bce_kernel(const float* __restrict__ y,
                           const float* __restrict__ t,
                           float* __restrict__ loss_out, int n)
{
    __shared__ float red[1024];
    float acc = 0.f;
    for (int i = threadIdx.x; i < n; i += 1024) {
        float v  = y[i];
        float tt = t[i];
        acc += fmaxf(v, 0.f) - v * tt + log1pf(__expf(-fabsf(v)));
    }
    red[threadIdx.x] = acc;
    __syncthreads();
    for (int s = 512; s > 0; s >>= 1) {
        if (threadIdx.x < s) red[threadIdx.x] += red[threadIdx.x + s];
        __syncthreads();
    }
    if (threadIdx.x == 0) loss_out[0] = red[0] / (float)n;
}

extern "C" void kernel_launch(void* const* d_in, const int* in_sizes, int n_in,
                              void* d_out, int out_size)
{
    const float* x      = (const float*)d_in[0];
    const float* target = (const float*)d_in[1];
    // d_in[2] = text_inputs (unused)
    const float* U_w    = (const float*)d_in[3];
    const float* F_w    = (const float*)d_in[4];
    const float* f_b    = (const float*)d_in[5];
    float* out = (float*)d_out;

    cudaFuncSetAttribute(attn_mma_kernel,
                         cudaFuncAttributeMaxDynamicSharedMemorySize, SMEM_BYTES);

    prep_w<<<1024, 256>>>(U_w, F_w);
    prep_x<<<2048, 256>>>(x);

    dim3 grid((Yn + YT - 1) / YT, Bn);   // 70 x 8 = 560 CTAs
    attn_mma_kernel<<<grid, NT, SMEM_BYTES>>>(f_b, out);

    if (out_size > Bn * Yn)
        bce_kernel<<<1, 1024>>>(out, target, out + Bn * Yn, Bn * Yn);
}

// round 11
// speedup vs baseline: 3.1549x; 1.1308x over previous
#include <cuda_runtime.h>
#include <cuda_fp16.h>
#include <cstdint>

#define Bn 8
#define Ln 2500
#define Dn 512
#define Yn 8921
#define YT 64           // y per CTA
#define LT 128          // l per CTA tile
#define KC 64           // k per chunk (fp16 elems)
#define NCH (Dn / KC)   // 8 chunks
#define NTILES 20       // ceil(2500/128)
#define NT 256
#define ROWB 144                    // smem row stride bytes (128 data + 16 pad)
#define TW (64 * ROWB)              // 9216  (U/F tiles: 64 rows)
#define TX (128 * ROWB)             // 18432 (X tile: 128 rows)
#define OFF_U 0
#define OFF_F TW
#define OFF_X (2 * TW)
#define BUF_BYTES (2 * TW + TX)     // 36864
#define SMEM_BYTES (2 * BUF_BYTES)  // 73728 -> 2 CTAs/SM

// fp16 scratch (device globals; no runtime alloc)
__device__ __half g_u16[(size_t)Yn * Dn];
__device__ __half g_f16[(size_t)Yn * Dn];
__device__ __half g_x16[(size_t)Bn * Ln * Dn];

// mma.sync m16n8k16 fp16 inputs, fp32 accumulate (plain sm_80+ instruction)
#define MMA(D, A, B0, B1)                                                   \
    asm volatile(                                                           \
        "mma.sync.aligned.m16n8k16.row.col.f32.f16.f16.f32 "                \
        "{%0,%1,%2,%3}, {%4,%5,%6,%7}, {%8,%9}, {%0,%1,%2,%3};"             \
        : "+f"((D)[0]), "+f"((D)[1]), "+f"((D)[2]), "+f"((D)[3])            \
        : "r"((A)[0]), "r"((A)[1]), "r"((A)[2]), "r"((A)[3]),               \
          "r"(B0), "r"(B1))

#define LDSM4(R0, R1, R2, R3, addr)                                         \
    asm volatile(                                                           \
        "ldmatrix.sync.aligned.m8n8.x4.shared.b16 {%0,%1,%2,%3}, [%4];"     \
        : "=r"(R0), "=r"(R1), "=r"(R2), "=r"(R3) : "r"(addr))

static __device__ __forceinline__ void cp16(uint32_t dst, const void* src,
                                            bool v) {
    int sz = v ? 16 : 0;   // sz=0 -> zero-fill 16B, no gmem read
    asm volatile("cp.async.cg.shared.global [%0], [%1], 16, %2;"
                 :: "r"(dst), "l"(src), "r"(sz));
}
template <int N>
static __device__ __forceinline__ void cpwait() {
    asm volatile("cp.async.wait_group %0;" :: "n"(N) : "memory");
}
static __device__ __forceinline__ uint32_t smem_u32(const void* p) {
    uint32_t a;
    asm("{ .reg .u64 t; cvta.to.shared.u64 t, %1; cvt.u32.u64 %0, t; }"
        : "=r"(a) : "l"(p));
    return a;
}

// stage one k-chunk: U,F [64 x 64] + X [128 x 64] fp16 -> padded smem
static __device__ __forceinline__ void stage_chunk(
    uint32_t bufaddr, int tid, int b, int y0, int l0, int k0)
{
    const __half* u = g_u16 + (size_t)y0 * Dn;
    const __half* f = g_f16 + (size_t)y0 * Dn;
    const int limW = Yn - y0;
#pragma unroll
    for (int j = 0; j < 2; j++) {
        int idx = tid + j * NT;              // 0..511 = 64 rows x 8 segs
        int r = idx >> 3, seg = idx & 7;     // seg = 16B (8 fp16)
        uint32_t doff = (uint32_t)(r * ROWB + seg * 16);
        cp16(bufaddr + OFF_U + doff, u + (size_t)r * Dn + k0 + seg * 8, r < limW);
        cp16(bufaddr + OFF_F + doff, f + (size_t)r * Dn + k0 + seg * 8, r < limW);
    }
    const __half* xs = g_x16 + ((size_t)b * Ln + l0) * Dn;
    const int limX = Ln - l0;
#pragma unroll
    for (int j = 0; j < 4; j++) {
        int idx = tid + j * NT;              // 0..1023 = 128 rows x 8 segs
        int r = idx >> 3, seg = idx & 7;
        cp16(bufaddr + OFF_X + (uint32_t)(r * ROWB + seg * 16),
             xs + (size_t)r * Dn + k0 + seg * 8, r < limX);
    }
    asm volatile("cp.async.commit_group;" ::: "memory");
}

__global__ __launch_bounds__(NT, 2)
void attn_mma_kernel(const float* __restrict__ f_b, float* __restrict__ out)
{
    extern __shared__ float smem[];
    const uint32_t sbase = smem_u32(smem);
    const int tid  = threadIdx.x;
    const int lane = tid & 31;
    const int g    = lane >> 2;          // group id 0..7
    const int tg   = lane & 3;           // thread in group 0..3
    const int wid  = tid >> 5;
    const int wy   = wid >> 2;           // warp y index 0..1 (32 y each)
    const int wl   = wid & 3;            // warp l index 0..3 (32 l each)
    const int b    = blockIdx.y;
    const int y0   = blockIdx.x * YT;

    // ldmatrix per-lane address components (bytes)
    const int quad = lane >> 3, r8 = lane & 7;
    const uint32_t laneA = (uint32_t)((r8 + (quad & 1) * 8) * ROWB + (quad >> 1) * 16);
    const uint32_t laneB = (uint32_t)((r8 + (quad >> 1) * 8) * ROWB + (quad & 1) * 16);
    uint32_t aRow[2], bRow[2];
#pragma unroll
    for (int a = 0; a < 2; a++)  aRow[a]  = (uint32_t)((wy * 32 + a * 16) * ROWB) + laneA;
#pragma unroll
    for (int cp = 0; cp < 2; cp++) bRow[cp] = (uint32_t)((wl * 32 + cp * 16) * ROWB) + laneB;

    // running softmax sums for this thread's 4 y rows
    float ss[4] = {0.f, 0.f, 0.f, 0.f};
    float zz[4] = {0.f, 0.f, 0.f, 0.f};

    stage_chunk(sbase, tid, b, y0, 0, 0);   // tile 0, chunk 0 -> buf 0

    for (int t = 0; t < NTILES; t++) {
        const int l0 = t * LT;

        float dS[2][4][4], dT[2][4][4];
#pragma unroll
        for (int a = 0; a < 2; a++)
#pragma unroll
            for (int c = 0; c < 4; c++)
#pragma unroll
                for (int r = 0; r < 4; r++) { dS[a][c][r] = 0.f; dT[a][c][r] = 0.f; }

        for (int ch = 0; ch < NCH; ch++) {
            cpwait<0>();
            __syncthreads();   // all warps done with the other buffer

            const bool last_all = (t == NTILES - 1) && (ch == NCH - 1);
            if (!last_all) {
                // prefetch next chunk (possibly next tile's chunk 0);
                // overlaps with this chunk's mma block
                int nl0 = (ch == NCH - 1) ? l0 + LT : l0;
                int nk0 = (ch == NCH - 1) ? 0 : (ch + 1) * KC;
                stage_chunk(sbase + ((ch + 1) & 1) * BUF_BYTES, tid, b, y0, nl0, nk0);
            }

            const uint32_t bufb = sbase + (ch & 1) * BUF_BYTES;

#pragma unroll
            for (int ka = 0; ka < 4; ka++) {        // four k16 steps
                const uint32_t kao = (uint32_t)(ka * 32);
                uint32_t au[2][4], af[2][4];
#pragma unroll
                for (int a = 0; a < 2; a++) {
                    uint32_t ab = bufb + aRow[a] + kao;
                    LDSM4(au[a][0], au[a][1], au[a][2], au[a][3], ab + OFF_U);
                    LDSM4(af[a][0], af[a][1], af[a][2], af[a][3], ab + OFF_F);
                }
                uint32_t bx[4][2];
#pragma unroll
                for (int cp = 0; cp < 2; cp++) {
                    uint32_t bb = bufb + OFF_X + bRow[cp] + kao;
                    LDSM4(bx[2*cp][0], bx[2*cp][1], bx[2*cp+1][0], bx[2*cp+1][1], bb);
                }
#pragma unroll
                for (int a = 0; a < 2; a++)
#pragma unroll
                    for (int c = 0; c < 4; c++) MMA(dS[a][c], au[a], bx[c][0], bx[c][1]);
#pragma unroll
                for (int a = 0; a < 2; a++)
#pragma unroll
                    for (int c = 0; c < 4; c++) MMA(dT[a][c], af[a], bx[c][0], bx[c][1]);
            }
        }

        // epilogue (regs only) — overlaps the in-flight prefetch of next tile
#pragma unroll
        for (int a = 0; a < 2; a++)
#pragma unroll
            for (int c = 0; c < 4; c++)
#pragma unroll
                for (int r2 = 0; r2 < 2; r2++) {
                    int le = l0 + wl * 32 + c * 8 + 2 * tg;
                    float s0 = dS[a][c][r2 * 2],     t0 = dT[a][c][r2 * 2];
                    float s1 = dS[a][c][r2 * 2 + 1], t1 = dT[a][c][r2 * 2 + 1];
                    if (le < Ln)     { float e = __expf(s0); ss[a*2+r2] += e; zz[a*2+r2] += e * t0; }
                    if (le + 1 < Ln) { float e = __expf(s1); ss[a*2+r2] += e; zz[a*2+r2] += e * t1; }
                }
    }

    // reduce across the 4 lanes sharing each y row (tg dimension)
#pragma unroll
    for (int i = 0; i < 4; i++) {
        ss[i] += __shfl_xor_sync(0xffffffffu, ss[i], 1);
        ss[i] += __shfl_xor_sync(0xffffffffu, ss[i], 2);
        zz[i] += __shfl_xor_sync(0xffffffffu, zz[i], 1);
        zz[i] += __shfl_xor_sync(0xffffffffu, zz[i], 2);
    }

    // cross-warp (wl) reduction via smem (all staging finished by now)
    __syncthreads();
    float* sred = smem;          // [4 wl][64]
    float* zred = smem + 256;    // [4 wl][64]
    if (tg == 0) {
#pragma unroll
        for (int i = 0; i < 4; i++) {
            int yl = wy * 32 + (i >> 1) * 16 + (i & 1) * 8 + g;
            sred[wl * 64 + yl] = ss[i];
            zred[wl * 64 + yl] = zz[i];
        }
    }
    __syncthreads();
    if (tid < YT) {
        int yg = y0 + tid;
        if (yg < Yn) {
            float s = sred[tid] + sred[64 + tid] + sred[128 + tid] + sred[192 + tid];
            float z = zred[tid] + zred[64 + tid] + zred[128 + tid] + zred[192 + tid];
            out[(size_t)b * Yn + yg] = z / s + f_b[yg];
        }
    }
}

// ---------------- prepass: fp32 -> fp16 ----------------
__global__ void prep_w(const float* __restrict__ U, const float* __restrict__ F)
{
    const size_t n = (size_t)Yn * Dn;
    for (size_t i = (size_t)blockIdx.x * blockDim.x + threadIdx.x; i < n;
         i += (size_t)gridDim.x * blockDim.x) {
        g_u16[i] = __float2half_rn(U[i]);
        g_f16[i] = __float2half_rn(F[i]);
    }
}

__global__ void prep_x(const float* __restrict__ x)
{
    const size_t n = (size_t)Bn * Ln * Dn;
    for (size_t i = (size_t)blockIdx.x * blockDim.x + threadIdx.x; i < n;
         i += (size_t)gridDim.x * blockDim.x)
        g_x16[i] = __float2half_rn(x[i]);
}

// mean BCE-with-logits; single block, fixed-order -> deterministic
__global__ void bce_kernel(const float* __restrict__ y,
                           const float* __restrict__ t,
                           float* __restrict__ loss_out, int n)
{
    __shared__ float red[1024];
    float acc = 0.f;
    for (int i = threadIdx.x; i < n; i += 1024) {
        float v  = y[i];
        float tt = t[i];
        acc += fmaxf(v, 0.f) - v * tt + log1pf(__expf(-fabsf(v)));
    }
    red[threadIdx.x] = acc;
    __syncthreads();
    for (int s = 512; s > 0; s >>= 1) {
        if (threadIdx.x < s) red[threadIdx.x] += red[threadIdx.x + s];
        __syncthreads();
    }
    if (threadIdx.x == 0) loss_out[0] = red[0] / (float)n;
}

extern "C" void kernel_launch(void* const* d_in, const int* in_sizes, int n_in,
                              void* d_out, int out_size)
{
    const float* x      = (const float*)d_in[0];
    const float* target = (const float*)d_in[1];
    // d_in[2] = text_inputs (unused)
    const float* U_w    = (const float*)d_in[3];
    const float* F_w    = (const float*)d_in[4];
    const float* f_b    = (const float*)d_in[5];
    float* out = (float*)d_out;

    cudaFuncSetAttribute(attn_mma_kernel,
                         cudaFuncAttributeMaxDynamicSharedMemorySize, SMEM_BYTES);

    prep_w<<<1024, 256>>>(U_w, F_w);
    prep_x<<<2048, 256>>>(x);

    dim3 grid((Yn + YT - 1) / YT, Bn);   // 140 x 8 = 1120 CTAs, 2/SM
    attn_mma_kernel<<<grid, NT, SMEM_BYTES>>>(f_b, out);

    if (out_size > Bn * Yn)
        bce_kernel<<<1, 1024>>>(out, target, out + Bn * Yn, Bn * Yn);
}